// round 14
// baseline (speedup 1.0000x reference)
#include <cuda_runtime.h>
#include <cuda_bf16.h>
#include <cstdint>
#include <math.h>

// GCRNN cell: B=64, N=4096, F=2, U=16, S=2
// R13 base + bf16 intermediates: D1/D2 stored bf16 (halves epilogue/gate
// traffic), g_H eliminated (epi2 re-reads h from D1). g_U stays fp32.

#define NN 4096
#define NCOL1 1152   // B*18
#define NCOL2 1024   // B*16
#define BM 128
#define BN 128
#define BKT 64
#define NT (NN / BKT)          // 64
#define ROW_B 144              // 64 bf16 + pad = 144 B/row
#define A_BYTES (BM * ROW_B)   // 18432
#define STG_BYTES (2 * A_BYTES)    // 36864
#define SMEM_TOT (3 * STG_BYTES)   // 110592 -> 2 CTAs/SM

__device__ __nv_bfloat16 g_Sbf[2ull * NN * NN];      // supports bf16 row-major
__device__ __nv_bfloat16 g_X1[(size_t)NCOL1 * NN];   // col-major [col][n]
__device__ __nv_bfloat16 g_X2[(size_t)NCOL2 * NN];
__device__ __nv_bfloat16 g_D1[2ull * NCOL1 * NN];    // [z][col][m] bf16
__device__ __nv_bfloat16 g_D2[2ull * NCOL2 * NN];    // [z][col][m] bf16
__device__ float g_U[(size_t)NCOL2 * NN];            // [b*16+u][m] fp32

// -------------------------------------------------------------- probe ----
__global__ void probe() { if (threadIdx.x == 1024) g_U[0] = 1.f; }

// ------------------------------------------------------------ convert ----
__global__ __launch_bounds__(256) void conv_sup(const float* __restrict__ S0,
                                                const float* __restrict__ S1) {
    const float* S = blockIdx.y ? S1 : S0;
    __nv_bfloat16* D = g_Sbf + (size_t)blockIdx.y * NN * NN;
    size_t idx = (size_t)blockIdx.x * 256 + threadIdx.x;
    float4 v0 = ((const float4*)S)[idx * 2];
    float4 v1 = ((const float4*)S)[idx * 2 + 1];
    __nv_bfloat162 p[4];
    p[0] = __floats2bfloat162_rn(v0.x, v0.y);
    p[1] = __floats2bfloat162_rn(v0.z, v0.w);
    p[2] = __floats2bfloat162_rn(v1.x, v1.y);
    p[3] = __floats2bfloat162_rn(v1.z, v1.w);
    ((uint4*)D)[idx] = *(uint4*)p;
}

// --------------------------------------------------------------- pack ----
__global__ __launch_bounds__(256) void pack1(const float* __restrict__ inputs,
                                             const float* __restrict__ state) {
    int idx = blockIdx.x * blockDim.x + threadIdx.x;
    int n = idx & 4095;
    int col = idx >> 12;              // 0..1151
    int b = col / 18;
    int c = col - b * 18;
    float v = (c < 2) ? inputs[b * 8192 + c * 4096 + n]
                      : state[b * 65536 + (c - 2) * 4096 + n];
    g_X1[(size_t)col * NN + n] = __float2bfloat16_rn(v);
}

// --------------------------------------------------------------- gemm ----
__device__ __forceinline__ void cp16s(uint32_t dst, const void* src) {
    asm volatile("cp.async.cg.shared.global [%0], [%1], 16;\n" :: "r"(dst), "l"(src));
}
__device__ __forceinline__ void ldsm4(unsigned* r, uint32_t addr) {
    asm volatile("ldmatrix.sync.aligned.m8n8.x4.shared.b16 {%0,%1,%2,%3}, [%4];"
                 : "=r"(r[0]), "=r"(r[1]), "=r"(r[2]), "=r"(r[3]) : "r"(addr));
}

// D[z][col][m] = sum_k S_z[m][k] * X[col][k]   (bf16 output)
__global__ __launch_bounds__(256, 2) void gemm_bf16(
    const __nv_bfloat16* __restrict__ X, __nv_bfloat16* __restrict__ C, int ncol)
{
    extern __shared__ __align__(1024) char smem[];
    uint32_t sbase = (uint32_t)__cvta_generic_to_shared(smem);

    const __nv_bfloat16* A = g_Sbf + (size_t)blockIdx.z * NN * NN;
    __nv_bfloat16* Cb = C + (size_t)blockIdx.z * ncol * NN;
    const int m0 = blockIdx.x * BM;
    const int c0 = blockIdx.y * BN;
    const int tid = threadIdx.x;
    const int lane = tid & 31;
    const int warp = tid >> 5;
    const int wm = warp & 3;        // 4 x 32 rows
    const int wn = warp >> 2;       // 2 x 64 cols
    const int g = lane >> 2;
    const int t = lane & 3;

    const __nv_bfloat16* Ag0 = A + (size_t)m0 * NN;
    const __nv_bfloat16* Bg0 = X + (size_t)c0 * NN;

    float acc[2][8][4];
    #pragma unroll
    for (int mi = 0; mi < 2; mi++)
        #pragma unroll
        for (int ni = 0; ni < 8; ni++)
            #pragma unroll
            for (int q = 0; q < 4; q++) acc[mi][ni][q] = 0.f;

    uint32_t aOff[2], bOff[4];
    #pragma unroll
    for (int mi = 0; mi < 2; mi++)
        aOff[mi] = (wm * 32 + mi * 16 + (lane & 15)) * ROW_B + ((lane >> 4) & 1) * 16;
    #pragma unroll
    for (int p = 0; p < 4; p++)
        bOff[p] = A_BYTES +
                  (wn * 64 + p * 16 + (lane & 7) + ((lane >> 4) & 1) * 8) * ROW_B +
                  ((lane >> 3) & 1) * 16;

    // part p in 0..3: p<2 -> A chunks {2p,2p+1}; p>=2 -> B chunks {2p-4,2p-3}
    auto stage_part = [&](int kt, int buf, int p) {
        uint32_t sA = sbase + buf * STG_BYTES;
        const __nv_bfloat16* Ags = Ag0 + kt * BKT;
        const __nv_bfloat16* Bgs = Bg0 + kt * BKT;
        #pragma unroll
        for (int j = 0; j < 2; j++) {
            if (p < 2) {
                int q = tid + (2 * p + j) * 256;
                int r = q >> 3, c = q & 7;
                cp16s(sA + r * ROW_B + c * 16, Ags + (size_t)r * NN + c * 8);
            } else {
                int q = tid + (2 * (p - 2) + j) * 256;
                int r = q >> 3, c = q & 7;
                cp16s(sA + A_BYTES + r * ROW_B + c * 16,
                      Bgs + (size_t)r * NN + c * 8);
            }
        }
    };

    #pragma unroll
    for (int p = 0; p < 4; p++) stage_part(0, 0, p);
    asm volatile("cp.async.commit_group;\n" ::: "memory");
    #pragma unroll
    for (int p = 0; p < 4; p++) stage_part(1, 1, p);
    asm volatile("cp.async.commit_group;\n" ::: "memory");

    for (int kt = 0; kt < NT; kt++) {
        asm volatile("cp.async.wait_group 1;\n" ::: "memory");
        __syncthreads();   // tile kt visible; buffer (kt+2)%3 drained

        uint32_t sb = sbase + (kt % 3) * STG_BYTES;
        const bool pf = (kt + 2 < NT);
        const int pbuf = (kt + 2) % 3;

        #pragma unroll
        for (int kk = 0; kk < 4; kk++) {
            unsigned a[2][4], b[8][2];
            #pragma unroll
            for (int mi = 0; mi < 2; mi++)
                ldsm4(a[mi], sb + aOff[mi] + kk * 32);
            #pragma unroll
            for (int p = 0; p < 4; p++) {
                unsigned r[4];
                ldsm4(r, sb + bOff[p] + kk * 32);
                b[2 * p][0] = r[0]; b[2 * p][1] = r[1];
                b[2 * p + 1][0] = r[2]; b[2 * p + 1][1] = r[3];
            }
            if (pf) stage_part(kt + 2, pbuf, kk);   // after ldsm, before mma

            #pragma unroll
            for (int mi = 0; mi < 2; mi++)
                #pragma unroll
                for (int ni = 0; ni < 8; ni++) {
                    asm volatile(
                        "mma.sync.aligned.m16n8k16.row.col.f32.bf16.bf16.f32 "
                        "{%0,%1,%2,%3}, {%4,%5,%6,%7}, {%8,%9}, {%0,%1,%2,%3};\n"
                        : "+f"(acc[mi][ni][0]), "+f"(acc[mi][ni][1]),
                          "+f"(acc[mi][ni][2]), "+f"(acc[mi][ni][3])
                        : "r"(a[mi][0]), "r"(a[mi][1]), "r"(a[mi][2]), "r"(a[mi][3]),
                          "r"(b[ni][0]), "r"(b[ni][1]));
                }
        }
        asm volatile("cp.async.commit_group;\n" ::: "memory");
    }

    // transposed store: D[col][m], bf16
    #pragma unroll
    for (int mi = 0; mi < 2; mi++) {
        int r0 = m0 + wm * 32 + mi * 16 + g;
        #pragma unroll
        for (int ni = 0; ni < 8; ni++) {
            int cc = c0 + wn * 64 + ni * 8 + t * 2;
            Cb[(size_t)cc * NN + r0]           = __float2bfloat16_rn(acc[mi][ni][0]);
            Cb[(size_t)(cc + 1) * NN + r0]     = __float2bfloat16_rn(acc[mi][ni][1]);
            Cb[(size_t)cc * NN + r0 + 8]       = __float2bfloat16_rn(acc[mi][ni][2]);
            Cb[(size_t)(cc + 1) * NN + r0 + 8] = __float2bfloat16_rn(acc[mi][ni][3]);
        }
    }
}

// ------------------------------------------------------------ fast math --
__device__ __forceinline__ float fsig(float x) {
    return __fdividef(1.f, 1.f + __expf(-x));
}
__device__ __forceinline__ float ftanh(float x) {
    float e = __expf(2.f * x);
    return __fdividef(e - 1.f, e + 1.f);
}
__device__ __forceinline__ unsigned long long pk2(float lo, float hi) {
    unsigned long long r;
    asm("mov.b64 %0, {%1, %2};" : "=l"(r) : "f"(lo), "f"(hi));
    return r;
}
__device__ __forceinline__ void upk2(unsigned long long v, float& lo, float& hi) {
    asm("mov.b64 {%0, %1}, %2;" : "=f"(lo), "=f"(hi) : "l"(v));
}
__device__ __forceinline__ unsigned long long ffma2(unsigned long long a,
                                                    unsigned long long b,
                                                    unsigned long long c) {
    unsigned long long d;
    asm("fma.rn.f32x2 %0, %1, %2, %3;" : "=l"(d) : "l"(a), "l"(b), "l"(c));
    return d;
}

// ---------------------------------------------------------------- epi 1 ---
// Two-pass (R then U), packed f32x2 FMA over u-pairs; D1 bf16.
__global__ __launch_bounds__(256) void epi1(const float* __restrict__ state,
                                            const float* __restrict__ rk,
                                            const float* __restrict__ uk)
{
    __shared__ __align__(8) float srk[576], suk[576];
    for (int i = threadIdx.x; i < 576; i += 256) { srk[i] = rk[i]; suk[i] = uk[i]; }
    __syncthreads();

    int idx = blockIdx.x * blockDim.x + threadIdx.x;  // b*4096 + m
    int m = idx & 4095;
    int b = idx >> 12;

    float hs[36];
    #pragma unroll
    for (int s = 0; s < 2; s++) {
        const __nv_bfloat16* d = g_D1 + ((size_t)(s * NCOL1 + b * 18)) * NN + m;
        hs[s * 2 + 0] = __bfloat162float(d[0]);
        hs[s * 2 + 1] = __bfloat162float(d[(size_t)NN]);
        #pragma unroll
        for (int u = 0; u < 16; u++)
            hs[4 + s * 16 + u] = __bfloat162float(d[(size_t)(2 + u) * NN]);
    }

    {
        unsigned long long aR[8];
        #pragma unroll
        for (int p = 0; p < 8; p++) aR[p] = 0ull;
        #pragma unroll
        for (int j = 0; j < 36; j++) {
            unsigned long long hh = pk2(hs[j], hs[j]);
            const unsigned long long* w = (const unsigned long long*)&srk[j * 16];
            #pragma unroll
            for (int p = 0; p < 8; p++) aR[p] = ffma2(hh, w[p], aR[p]);
        }
        #pragma unroll
        for (int p = 0; p < 8; p++) {
            float x, y;
            upk2(aR[p], x, y);
            float r0 = fsig(x), r1 = fsig(y);
            float pv0 = state[b * 65536 + (2 * p) * 4096 + m];
            float pv1 = state[b * 65536 + (2 * p + 1) * 4096 + m];
            g_X2[(size_t)(b * 16 + 2 * p) * NN + m]     = __float2bfloat16_rn(r0 * pv0);
            g_X2[(size_t)(b * 16 + 2 * p + 1) * NN + m] = __float2bfloat16_rn(r1 * pv1);
        }
    }
    {
        unsigned long long aU[8];
        #pragma unroll
        for (int p = 0; p < 8; p++) aU[p] = 0ull;
        #pragma unroll
        for (int j = 0; j < 36; j++) {
            unsigned long long hh = pk2(hs[j], hs[j]);
            const unsigned long long* w = (const unsigned long long*)&suk[j * 16];
            #pragma unroll
            for (int p = 0; p < 8; p++) aU[p] = ffma2(hh, w[p], aU[p]);
        }
        #pragma unroll
        for (int p = 0; p < 8; p++) {
            float x, y;
            upk2(aU[p], x, y);
            g_U[(size_t)(b * 16 + 2 * p) * NN + m]     = fsig(x);
            g_U[(size_t)(b * 16 + 2 * p + 1) * NN + m] = fsig(y);
        }
    }
}

// ---------------------------------------------------------------- epi 2 ---
// h re-read from D1 (bf16); c_state from D2 (bf16).
__global__ __launch_bounds__(256) void epi2(const float* __restrict__ state,
                                            const float* __restrict__ ck,
                                            float* __restrict__ out)
{
    __shared__ __align__(8) float sck[576];
    for (int i = threadIdx.x; i < 576; i += 256) sck[i] = ck[i];
    __syncthreads();

    int idx = blockIdx.x * blockDim.x + threadIdx.x;  // b*4096 + m
    int m = idx & 4095;
    int b = idx >> 12;

    float hs[36];
    #pragma unroll
    for (int s = 0; s < 2; s++) {
        const __nv_bfloat16* d1 = g_D1 + ((size_t)(s * NCOL1 + b * 18)) * NN + m;
        hs[s * 2 + 0] = __bfloat162float(d1[0]);
        hs[s * 2 + 1] = __bfloat162float(d1[(size_t)NN]);
        const __nv_bfloat16* d2 = g_D2 + ((size_t)(s * NCOL2 + b * 16)) * NN + m;
        #pragma unroll
        for (int u = 0; u < 16; u++)
            hs[4 + s * 16 + u] = __bfloat162float(d2[(size_t)u * NN]);
    }

    unsigned long long aC[8];
    #pragma unroll
    for (int p = 0; p < 8; p++) aC[p] = 0ull;
    #pragma unroll
    for (int j = 0; j < 36; j++) {
        unsigned long long hh = pk2(hs[j], hs[j]);
        const unsigned long long* w = (const unsigned long long*)&sck[j * 16];
        #pragma unroll
        for (int p = 0; p < 8; p++) aC[p] = ffma2(hh, w[p], aC[p]);
    }
    float4 o[4];
    #pragma unroll
    for (int p = 0; p < 8; p++) {
        float x, y;
        upk2(aC[p], x, y);
        float c0 = ftanh(x), c1 = ftanh(y);
        float u0 = g_U[(size_t)(b * 16 + 2 * p) * NN + m];
        float u1 = g_U[(size_t)(b * 16 + 2 * p + 1) * NN + m];
        float p0 = state[b * 65536 + (2 * p) * 4096 + m];
        float p1 = state[b * 65536 + (2 * p + 1) * 4096 + m];
        ((float*)o)[2 * p]     = u0 * p0 + (1.f - u0) * c0;
        ((float*)o)[2 * p + 1] = u1 * p1 + (1.f - u1) * c1;
    }
    float4* dst = (float4*)&out[b * 65536 + m * 16];
    #pragma unroll
    for (int q = 0; q < 4; q++) dst[q] = o[q];
}

// -------------------------------------------------------------- launch ----
extern "C" void kernel_launch(void* const* d_in, const int* in_sizes, int n_in,
                              void* d_out, int out_size) {
    const float* inputs = (const float*)d_in[0];
    const float* state  = (const float*)d_in[1];
    const float* s0     = (const float*)d_in[2];
    const float* s1     = (const float*)d_in[3];
    const float* rk     = (const float*)d_in[4];
    const float* uk     = (const float*)d_in[5];
    const float* ck     = (const float*)d_in[6];
    float* out = (float*)d_out;

    cudaFuncSetAttribute(gemm_bf16, cudaFuncAttributeMaxDynamicSharedMemorySize,
                         SMEM_TOT);

    __nv_bfloat16 *x1, *x2, *d1, *d2;
    cudaGetSymbolAddress((void**)&x1, g_X1);
    cudaGetSymbolAddress((void**)&x2, g_X2);
    cudaGetSymbolAddress((void**)&d1, g_D1);
    cudaGetSymbolAddress((void**)&d2, g_D2);

    probe<<<1, 32>>>();
    conv_sup<<<dim3(NN * NN / (256 * 8), 2), 256>>>(s0, s1);
    pack1<<<(NN * NCOL1) / 256, 256>>>(inputs, state);
    gemm_bf16<<<dim3(NN / BM, NCOL1 / BN, 2), 256, SMEM_TOT>>>(x1, d1, NCOL1);
    epi1<<<(64 * NN) / 256, 256>>>(state, rk, uk);
    gemm_bf16<<<dim3(NN / BM, NCOL2 / BN, 2), 256, SMEM_TOT>>>(x2, d2, NCOL2);
    epi2<<<(64 * NN) / 256, 256>>>(state, ck, out);
}

// round 15
// speedup vs baseline: 1.0234x; 1.0234x over previous
#include <cuda_runtime.h>
#include <cuda_bf16.h>
#include <cstdint>
#include <math.h>

// GCRNN cell: B=64, N=4096, F=2, U=16, S=2
// R13 structure (best known): bf16 mma.sync m16n8k16 + ldmatrix, cp.async
// 3-stage spread per-kk, 2 CTAs/SM, fp32 D transposed [z][col][m], f32x2
// gate epilogues. This round: probe removed, conv_sup+pack1 fused.

#define NN 4096
#define NCOL1 1152   // B*18
#define NCOL2 1024   // B*16
#define BM 128
#define BN 128
#define BKT 64
#define NT (NN / BKT)          // 64
#define ROW_B 144              // 64 bf16 + pad = 144 B/row
#define A_BYTES (BM * ROW_B)   // 18432
#define STG_BYTES (2 * A_BYTES)    // 36864
#define SMEM_TOT (3 * STG_BYTES)   // 110592 -> 2 CTAs/SM

__device__ __nv_bfloat16 g_Sbf[2ull * NN * NN];      // supports bf16 row-major
__device__ __nv_bfloat16 g_X1[(size_t)NCOL1 * NN];   // col-major [col][n]
__device__ __nv_bfloat16 g_X2[(size_t)NCOL2 * NN];
__device__ float g_D1[2ull * NCOL1 * NN];            // [z][col][m]
__device__ float g_D2[2ull * NCOL2 * NN];            // [z][col][m]
__device__ float g_U[(size_t)NCOL2 * NN];            // [b*16+u][m]
__device__ float g_H[(size_t)256 * NN];              // [b*4+j][m]

// ----------------------------------------------- fused convert + pack ----
// blocks [0, 16384): convert supports to bf16 (8 float4-pairs per thread)
// blocks [16384, 16384+4608): pack X1 col-major bf16
#define CONV_BLKS 16384   // 2 supports * 16M elems / (256 thr * 8 elems)
#define PACK_BLKS ((NN / 256) * NCOL1 / 16 * 4)   // 4608: 1152*4096/(256*4)

__global__ __launch_bounds__(256) void convpack(const float* __restrict__ S0,
                                                const float* __restrict__ S1,
                                                const float* __restrict__ inputs,
                                                const float* __restrict__ state) {
    int blk = blockIdx.x;
    if (blk < CONV_BLKS) {
        int z = blk >> 13;                       // 8192 blocks per support
        const float* S = z ? S1 : S0;
        __nv_bfloat16* D = g_Sbf + (size_t)z * NN * NN;
        size_t idx = ((size_t)(blk & 8191)) * 256 + threadIdx.x;
        float4 v0 = ((const float4*)S)[idx * 2];
        float4 v1 = ((const float4*)S)[idx * 2 + 1];
        __nv_bfloat162 p[4];
        p[0] = __floats2bfloat162_rn(v0.x, v0.y);
        p[1] = __floats2bfloat162_rn(v0.z, v0.w);
        p[2] = __floats2bfloat162_rn(v1.x, v1.y);
        p[3] = __floats2bfloat162_rn(v1.z, v1.w);
        ((uint4*)D)[idx] = *(uint4*)p;
    } else {
        // 4 elements per thread along n
        int q = (blk - CONV_BLKS) * 256 + threadIdx.x;   // 1,179,648 quads
        int n4 = q & 1023;                               // 1024 quads of 4
        int col = q >> 10;                               // 0..1151
        int b = col / 18;
        int c = col - b * 18;
        const float* src = (c < 2) ? inputs + b * 8192 + c * 4096
                                   : state + b * 65536 + (c - 2) * 4096;
        float4 v = ((const float4*)src)[n4];
        __nv_bfloat162 p[2];
        p[0] = __floats2bfloat162_rn(v.x, v.y);
        p[1] = __floats2bfloat162_rn(v.z, v.w);
        ((uint2*)(g_X1 + (size_t)col * NN))[n4] = *(uint2*)p;
    }
}

// --------------------------------------------------------------- gemm ----
__device__ __forceinline__ void cp16s(uint32_t dst, const void* src) {
    asm volatile("cp.async.cg.shared.global [%0], [%1], 16;\n" :: "r"(dst), "l"(src));
}
__device__ __forceinline__ void ldsm4(unsigned* r, uint32_t addr) {
    asm volatile("ldmatrix.sync.aligned.m8n8.x4.shared.b16 {%0,%1,%2,%3}, [%4];"
                 : "=r"(r[0]), "=r"(r[1]), "=r"(r[2]), "=r"(r[3]) : "r"(addr));
}

// D[z][col][m] = sum_k S_z[m][k] * X[col][k]
__global__ __launch_bounds__(256, 2) void gemm_bf16(
    const __nv_bfloat16* __restrict__ X, float* __restrict__ C, int ncol)
{
    extern __shared__ __align__(1024) char smem[];
    uint32_t sbase = (uint32_t)__cvta_generic_to_shared(smem);

    const __nv_bfloat16* A = g_Sbf + (size_t)blockIdx.z * NN * NN;
    float* Cb = C + (size_t)blockIdx.z * ncol * NN;
    const int m0 = blockIdx.x * BM;
    const int c0 = blockIdx.y * BN;
    const int tid = threadIdx.x;
    const int lane = tid & 31;
    const int warp = tid >> 5;
    const int wm = warp & 3;        // 4 x 32 rows
    const int wn = warp >> 2;       // 2 x 64 cols
    const int g = lane >> 2;
    const int t = lane & 3;

    const __nv_bfloat16* Ag0 = A + (size_t)m0 * NN;
    const __nv_bfloat16* Bg0 = X + (size_t)c0 * NN;

    float acc[2][8][4];
    #pragma unroll
    for (int mi = 0; mi < 2; mi++)
        #pragma unroll
        for (int ni = 0; ni < 8; ni++)
            #pragma unroll
            for (int q = 0; q < 4; q++) acc[mi][ni][q] = 0.f;

    uint32_t aOff[2], bOff[4];
    #pragma unroll
    for (int mi = 0; mi < 2; mi++)
        aOff[mi] = (wm * 32 + mi * 16 + (lane & 15)) * ROW_B + ((lane >> 4) & 1) * 16;
    #pragma unroll
    for (int p = 0; p < 4; p++)
        bOff[p] = A_BYTES +
                  (wn * 64 + p * 16 + (lane & 7) + ((lane >> 4) & 1) * 8) * ROW_B +
                  ((lane >> 3) & 1) * 16;

    // part p in 0..3: p<2 -> A chunks {2p,2p+1}; p>=2 -> B chunks {2p-4,2p-3}
    auto stage_part = [&](int kt, int buf, int p) {
        uint32_t sA = sbase + buf * STG_BYTES;
        const __nv_bfloat16* Ags = Ag0 + kt * BKT;
        const __nv_bfloat16* Bgs = Bg0 + kt * BKT;
        #pragma unroll
        for (int j = 0; j < 2; j++) {
            if (p < 2) {
                int q = tid + (2 * p + j) * 256;
                int r = q >> 3, c = q & 7;
                cp16s(sA + r * ROW_B + c * 16, Ags + (size_t)r * NN + c * 8);
            } else {
                int q = tid + (2 * (p - 2) + j) * 256;
                int r = q >> 3, c = q & 7;
                cp16s(sA + A_BYTES + r * ROW_B + c * 16,
                      Bgs + (size_t)r * NN + c * 8);
            }
        }
    };

    #pragma unroll
    for (int p = 0; p < 4; p++) stage_part(0, 0, p);
    asm volatile("cp.async.commit_group;\n" ::: "memory");
    #pragma unroll
    for (int p = 0; p < 4; p++) stage_part(1, 1, p);
    asm volatile("cp.async.commit_group;\n" ::: "memory");

    for (int kt = 0; kt < NT; kt++) {
        asm volatile("cp.async.wait_group 1;\n" ::: "memory");
        __syncthreads();   // tile kt visible; buffer (kt+2)%3 drained

        uint32_t sb = sbase + (kt % 3) * STG_BYTES;
        const bool pf = (kt + 2 < NT);
        const int pbuf = (kt + 2) % 3;

        #pragma unroll
        for (int kk = 0; kk < 4; kk++) {
            unsigned a[2][4], b[8][2];
            #pragma unroll
            for (int mi = 0; mi < 2; mi++)
                ldsm4(a[mi], sb + aOff[mi] + kk * 32);
            #pragma unroll
            for (int p = 0; p < 4; p++) {
                unsigned r[4];
                ldsm4(r, sb + bOff[p] + kk * 32);
                b[2 * p][0] = r[0]; b[2 * p][1] = r[1];
                b[2 * p + 1][0] = r[2]; b[2 * p + 1][1] = r[3];
            }
            if (pf) stage_part(kt + 2, pbuf, kk);   // after ldsm, before mma

            #pragma unroll
            for (int mi = 0; mi < 2; mi++)
                #pragma unroll
                for (int ni = 0; ni < 8; ni++) {
                    asm volatile(
                        "mma.sync.aligned.m16n8k16.row.col.f32.bf16.bf16.f32 "
                        "{%0,%1,%2,%3}, {%4,%5,%6,%7}, {%8,%9}, {%0,%1,%2,%3};\n"
                        : "+f"(acc[mi][ni][0]), "+f"(acc[mi][ni][1]),
                          "+f"(acc[mi][ni][2]), "+f"(acc[mi][ni][3])
                        : "r"(a[mi][0]), "r"(a[mi][1]), "r"(a[mi][2]), "r"(a[mi][3]),
                          "r"(b[ni][0]), "r"(b[ni][1]));
                }
        }
        asm volatile("cp.async.commit_group;\n" ::: "memory");
    }

    // transposed store: D[col][m]
    #pragma unroll
    for (int mi = 0; mi < 2; mi++) {
        int r0 = m0 + wm * 32 + mi * 16 + g;
        #pragma unroll
        for (int ni = 0; ni < 8; ni++) {
            int cc = c0 + wn * 64 + ni * 8 + t * 2;
            Cb[(size_t)cc * NN + r0]           = acc[mi][ni][0];
            Cb[(size_t)(cc + 1) * NN + r0]     = acc[mi][ni][1];
            Cb[(size_t)cc * NN + r0 + 8]       = acc[mi][ni][2];
            Cb[(size_t)(cc + 1) * NN + r0 + 8] = acc[mi][ni][3];
        }
    }
}

// ------------------------------------------------------------ fast math --
__device__ __forceinline__ float fsig(float x) {
    return __fdividef(1.f, 1.f + __expf(-x));
}
__device__ __forceinline__ float ftanh(float x) {
    float e = __expf(2.f * x);
    return __fdividef(e - 1.f, e + 1.f);
}
__device__ __forceinline__ unsigned long long pk2(float lo, float hi) {
    unsigned long long r;
    asm("mov.b64 %0, {%1, %2};" : "=l"(r) : "f"(lo), "f"(hi));
    return r;
}
__device__ __forceinline__ void upk2(unsigned long long v, float& lo, float& hi) {
    asm("mov.b64 {%0, %1}, %2;" : "=f"(lo), "=f"(hi) : "l"(v));
}
__device__ __forceinline__ unsigned long long ffma2(unsigned long long a,
                                                    unsigned long long b,
                                                    unsigned long long c) {
    unsigned long long d;
    asm("fma.rn.f32x2 %0, %1, %2, %3;" : "=l"(d) : "l"(a), "l"(b), "l"(c));
    return d;
}

// ---------------------------------------------------------------- epi 1 ---
// Two-pass (R then U), packed f32x2 FMA over u-pairs.
__global__ __launch_bounds__(256) void epi1(const float* __restrict__ state,
                                            const float* __restrict__ rk,
                                            const float* __restrict__ uk)
{
    __shared__ __align__(8) float srk[576], suk[576];
    for (int i = threadIdx.x; i < 576; i += 256) { srk[i] = rk[i]; suk[i] = uk[i]; }
    __syncthreads();

    int idx = blockIdx.x * blockDim.x + threadIdx.x;  // b*4096 + m
    int m = idx & 4095;
    int b = idx >> 12;

    float hs[36];
    #pragma unroll
    for (int s = 0; s < 2; s++) {
        const float* d = g_D1 + ((size_t)(s * NCOL1 + b * 18)) * NN + m;
        hs[s * 2 + 0] = d[0];
        hs[s * 2 + 1] = d[(size_t)NN];
        #pragma unroll
        for (int u = 0; u < 16; u++) hs[4 + s * 16 + u] = d[(size_t)(2 + u) * NN];
    }

    {
        unsigned long long aR[8];
        #pragma unroll
        for (int p = 0; p < 8; p++) aR[p] = 0ull;
        #pragma unroll
        for (int j = 0; j < 36; j++) {
            unsigned long long hh = pk2(hs[j], hs[j]);
            const unsigned long long* w = (const unsigned long long*)&srk[j * 16];
            #pragma unroll
            for (int p = 0; p < 8; p++) aR[p] = ffma2(hh, w[p], aR[p]);
        }
        #pragma unroll
        for (int p = 0; p < 8; p++) {
            float x, y;
            upk2(aR[p], x, y);
            float r0 = fsig(x), r1 = fsig(y);
            float pv0 = state[b * 65536 + (2 * p) * 4096 + m];
            float pv1 = state[b * 65536 + (2 * p + 1) * 4096 + m];
            g_X2[(size_t)(b * 16 + 2 * p) * NN + m]     = __float2bfloat16_rn(r0 * pv0);
            g_X2[(size_t)(b * 16 + 2 * p + 1) * NN + m] = __float2bfloat16_rn(r1 * pv1);
        }
    }
    {
        unsigned long long aU[8];
        #pragma unroll
        for (int p = 0; p < 8; p++) aU[p] = 0ull;
        #pragma unroll
        for (int j = 0; j < 36; j++) {
            unsigned long long hh = pk2(hs[j], hs[j]);
            const unsigned long long* w = (const unsigned long long*)&suk[j * 16];
            #pragma unroll
            for (int p = 0; p < 8; p++) aU[p] = ffma2(hh, w[p], aU[p]);
        }
        #pragma unroll
        for (int p = 0; p < 8; p++) {
            float x, y;
            upk2(aU[p], x, y);
            g_U[(size_t)(b * 16 + 2 * p) * NN + m]     = fsig(x);
            g_U[(size_t)(b * 16 + 2 * p + 1) * NN + m] = fsig(y);
        }
    }
    #pragma unroll
    for (int j = 0; j < 4; j++) g_H[(size_t)(b * 4 + j) * NN + m] = hs[j];
}

// ---------------------------------------------------------------- epi 2 ---
__global__ __launch_bounds__(256) void epi2(const float* __restrict__ state,
                                            const float* __restrict__ ck,
                                            float* __restrict__ out)
{
    __shared__ __align__(8) float sck[576];
    for (int i = threadIdx.x; i < 576; i += 256) sck[i] = ck[i];
    __syncthreads();

    int idx = blockIdx.x * blockDim.x + threadIdx.x;  // b*4096 + m
    int m = idx & 4095;
    int b = idx >> 12;

    float hs[36];
    #pragma unroll
    for (int j = 0; j < 4; j++) hs[j] = g_H[(size_t)(b * 4 + j) * NN + m];
    #pragma unroll
    for (int s = 0; s < 2; s++) {
        const float* d = g_D2 + ((size_t)(s * NCOL2 + b * 16)) * NN + m;
        #pragma unroll
        for (int u = 0; u < 16; u++) hs[4 + s * 16 + u] = d[(size_t)u * NN];
    }

    unsigned long long aC[8];
    #pragma unroll
    for (int p = 0; p < 8; p++) aC[p] = 0ull;
    #pragma unroll
    for (int j = 0; j < 36; j++) {
        unsigned long long hh = pk2(hs[j], hs[j]);
        const unsigned long long* w = (const unsigned long long*)&sck[j * 16];
        #pragma unroll
        for (int p = 0; p < 8; p++) aC[p] = ffma2(hh, w[p], aC[p]);
    }
    float4 o[4];
    #pragma unroll
    for (int p = 0; p < 8; p++) {
        float x, y;
        upk2(aC[p], x, y);
        float c0 = ftanh(x), c1 = ftanh(y);
        float u0 = g_U[(size_t)(b * 16 + 2 * p) * NN + m];
        float u1 = g_U[(size_t)(b * 16 + 2 * p + 1) * NN + m];
        float p0 = state[b * 65536 + (2 * p) * 4096 + m];
        float p1 = state[b * 65536 + (2 * p + 1) * 4096 + m];
        ((float*)o)[2 * p]     = u0 * p0 + (1.f - u0) * c0;
        ((float*)o)[2 * p + 1] = u1 * p1 + (1.f - u1) * c1;
    }
    float4* dst = (float4*)&out[b * 65536 + m * 16];
    #pragma unroll
    for (int q = 0; q < 4; q++) dst[q] = o[q];
}

// -------------------------------------------------------------- launch ----
extern "C" void kernel_launch(void* const* d_in, const int* in_sizes, int n_in,
                              void* d_out, int out_size) {
    const float* inputs = (const float*)d_in[0];
    const float* state  = (const float*)d_in[1];
    const float* s0     = (const float*)d_in[2];
    const float* s1     = (const float*)d_in[3];
    const float* rk     = (const float*)d_in[4];
    const float* uk     = (const float*)d_in[5];
    const float* ck     = (const float*)d_in[6];
    float* out = (float*)d_out;

    cudaFuncSetAttribute(gemm_bf16, cudaFuncAttributeMaxDynamicSharedMemorySize,
                         SMEM_TOT);

    __nv_bfloat16 *x1, *x2;
    float *d1, *d2;
    cudaGetSymbolAddress((void**)&x1, g_X1);
    cudaGetSymbolAddress((void**)&x2, g_X2);
    cudaGetSymbolAddress((void**)&d1, g_D1);
    cudaGetSymbolAddress((void**)&d2, g_D2);

    convpack<<<CONV_BLKS + PACK_BLKS, 256>>>(s0, s1, inputs, state);
    gemm_bf16<<<dim3(NN / BM, NCOL1 / BN, 2), 256, SMEM_TOT>>>(x1, d1, NCOL1);
    epi1<<<(64 * NN) / 256, 256>>>(state, rk, uk);
    gemm_bf16<<<dim3(NN / BM, NCOL2 / BN, 2), 256, SMEM_TOT>>>(x2, d2, NCOL2);
    epi2<<<(64 * NN) / 256, 256>>>(state, ck, out);
}

// round 16
// speedup vs baseline: 1.0376x; 1.0139x over previous
#include <cuda_runtime.h>
#include <cuda_bf16.h>
#include <cstdint>
#include <math.h>

// GCRNN cell: B=64, N=4096, F=2, U=16, S=2
// R15 base: bf16 mma.sync m16n8k16 + ldmatrix, cp.async 3-stage spread
// per-kk, 2 CTAs/SM, fp32 D transposed [z][col][m], f32x2 gate epilogues,
// fused convpack. This round: epis reg-capped (256,3), g_H dropped (epi2
// re-reads h from D1).

#define NN 4096
#define NCOL1 1152   // B*18
#define NCOL2 1024   // B*16
#define BM 128
#define BN 128
#define BKT 64
#define NT (NN / BKT)          // 64
#define ROW_B 144              // 64 bf16 + pad = 144 B/row
#define A_BYTES (BM * ROW_B)   // 18432
#define STG_BYTES (2 * A_BYTES)    // 36864
#define SMEM_TOT (3 * STG_BYTES)   // 110592 -> 2 CTAs/SM

__device__ __nv_bfloat16 g_Sbf[2ull * NN * NN];      // supports bf16 row-major
__device__ __nv_bfloat16 g_X1[(size_t)NCOL1 * NN];   // col-major [col][n]
__device__ __nv_bfloat16 g_X2[(size_t)NCOL2 * NN];
__device__ float g_D1[2ull * NCOL1 * NN];            // [z][col][m]
__device__ float g_D2[2ull * NCOL2 * NN];            // [z][col][m]
__device__ float g_U[(size_t)NCOL2 * NN];            // [b*16+u][m]

// ----------------------------------------------- fused convert + pack ----
#define CONV_BLKS 16384   // 2 supports * 16M elems / (256 thr * 8 elems)
#define PACK_BLKS 4608    // 1152*4096/(256*4)

__global__ __launch_bounds__(256) void convpack(const float* __restrict__ S0,
                                                const float* __restrict__ S1,
                                                const float* __restrict__ inputs,
                                                const float* __restrict__ state) {
    int blk = blockIdx.x;
    if (blk < CONV_BLKS) {
        int z = blk >> 13;
        const float* S = z ? S1 : S0;
        __nv_bfloat16* D = g_Sbf + (size_t)z * NN * NN;
        size_t idx = ((size_t)(blk & 8191)) * 256 + threadIdx.x;
        float4 v0 = ((const float4*)S)[idx * 2];
        float4 v1 = ((const float4*)S)[idx * 2 + 1];
        __nv_bfloat162 p[4];
        p[0] = __floats2bfloat162_rn(v0.x, v0.y);
        p[1] = __floats2bfloat162_rn(v0.z, v0.w);
        p[2] = __floats2bfloat162_rn(v1.x, v1.y);
        p[3] = __floats2bfloat162_rn(v1.z, v1.w);
        ((uint4*)D)[idx] = *(uint4*)p;
    } else {
        int q = (blk - CONV_BLKS) * 256 + threadIdx.x;
        int n4 = q & 1023;
        int col = q >> 10;              // 0..1151
        int b = col / 18;
        int c = col - b * 18;
        const float* src = (c < 2) ? inputs + b * 8192 + c * 4096
                                   : state + b * 65536 + (c - 2) * 4096;
        float4 v = ((const float4*)src)[n4];
        __nv_bfloat162 p[2];
        p[0] = __floats2bfloat162_rn(v.x, v.y);
        p[1] = __floats2bfloat162_rn(v.z, v.w);
        ((uint2*)(g_X1 + (size_t)col * NN))[n4] = *(uint2*)p;
    }
}

// --------------------------------------------------------------- gemm ----
__device__ __forceinline__ void cp16s(uint32_t dst, const void* src) {
    asm volatile("cp.async.cg.shared.global [%0], [%1], 16;\n" :: "r"(dst), "l"(src));
}
__device__ __forceinline__ void ldsm4(unsigned* r, uint32_t addr) {
    asm volatile("ldmatrix.sync.aligned.m8n8.x4.shared.b16 {%0,%1,%2,%3}, [%4];"
                 : "=r"(r[0]), "=r"(r[1]), "=r"(r[2]), "=r"(r[3]) : "r"(addr));
}

// D[z][col][m] = sum_k S_z[m][k] * X[col][k]
__global__ __launch_bounds__(256, 2) void gemm_bf16(
    const __nv_bfloat16* __restrict__ X, float* __restrict__ C, int ncol)
{
    extern __shared__ __align__(1024) char smem[];
    uint32_t sbase = (uint32_t)__cvta_generic_to_shared(smem);

    const __nv_bfloat16* A = g_Sbf + (size_t)blockIdx.z * NN * NN;
    float* Cb = C + (size_t)blockIdx.z * ncol * NN;
    const int m0 = blockIdx.x * BM;
    const int c0 = blockIdx.y * BN;
    const int tid = threadIdx.x;
    const int lane = tid & 31;
    const int warp = tid >> 5;
    const int wm = warp & 3;
    const int wn = warp >> 2;
    const int g = lane >> 2;
    const int t = lane & 3;

    const __nv_bfloat16* Ag0 = A + (size_t)m0 * NN;
    const __nv_bfloat16* Bg0 = X + (size_t)c0 * NN;

    float acc[2][8][4];
    #pragma unroll
    for (int mi = 0; mi < 2; mi++)
        #pragma unroll
        for (int ni = 0; ni < 8; ni++)
            #pragma unroll
            for (int q = 0; q < 4; q++) acc[mi][ni][q] = 0.f;

    uint32_t aOff[2], bOff[4];
    #pragma unroll
    for (int mi = 0; mi < 2; mi++)
        aOff[mi] = (wm * 32 + mi * 16 + (lane & 15)) * ROW_B + ((lane >> 4) & 1) * 16;
    #pragma unroll
    for (int p = 0; p < 4; p++)
        bOff[p] = A_BYTES +
                  (wn * 64 + p * 16 + (lane & 7) + ((lane >> 4) & 1) * 8) * ROW_B +
                  ((lane >> 3) & 1) * 16;

    auto stage_part = [&](int kt, int buf, int p) {
        uint32_t sA = sbase + buf * STG_BYTES;
        const __nv_bfloat16* Ags = Ag0 + kt * BKT;
        const __nv_bfloat16* Bgs = Bg0 + kt * BKT;
        #pragma unroll
        for (int j = 0; j < 2; j++) {
            if (p < 2) {
                int q = tid + (2 * p + j) * 256;
                int r = q >> 3, c = q & 7;
                cp16s(sA + r * ROW_B + c * 16, Ags + (size_t)r * NN + c * 8);
            } else {
                int q = tid + (2 * (p - 2) + j) * 256;
                int r = q >> 3, c = q & 7;
                cp16s(sA + A_BYTES + r * ROW_B + c * 16,
                      Bgs + (size_t)r * NN + c * 8);
            }
        }
    };

    #pragma unroll
    for (int p = 0; p < 4; p++) stage_part(0, 0, p);
    asm volatile("cp.async.commit_group;\n" ::: "memory");
    #pragma unroll
    for (int p = 0; p < 4; p++) stage_part(1, 1, p);
    asm volatile("cp.async.commit_group;\n" ::: "memory");

    for (int kt = 0; kt < NT; kt++) {
        asm volatile("cp.async.wait_group 1;\n" ::: "memory");
        __syncthreads();

        uint32_t sb = sbase + (kt % 3) * STG_BYTES;
        const bool pf = (kt + 2 < NT);
        const int pbuf = (kt + 2) % 3;

        #pragma unroll
        for (int kk = 0; kk < 4; kk++) {
            unsigned a[2][4], b[8][2];
            #pragma unroll
            for (int mi = 0; mi < 2; mi++)
                ldsm4(a[mi], sb + aOff[mi] + kk * 32);
            #pragma unroll
            for (int p = 0; p < 4; p++) {
                unsigned r[4];
                ldsm4(r, sb + bOff[p] + kk * 32);
                b[2 * p][0] = r[0]; b[2 * p][1] = r[1];
                b[2 * p + 1][0] = r[2]; b[2 * p + 1][1] = r[3];
            }
            if (pf) stage_part(kt + 2, pbuf, kk);

            #pragma unroll
            for (int mi = 0; mi < 2; mi++)
                #pragma unroll
                for (int ni = 0; ni < 8; ni++) {
                    asm volatile(
                        "mma.sync.aligned.m16n8k16.row.col.f32.bf16.bf16.f32 "
                        "{%0,%1,%2,%3}, {%4,%5,%6,%7}, {%8,%9}, {%0,%1,%2,%3};\n"
                        : "+f"(acc[mi][ni][0]), "+f"(acc[mi][ni][1]),
                          "+f"(acc[mi][ni][2]), "+f"(acc[mi][ni][3])
                        : "r"(a[mi][0]), "r"(a[mi][1]), "r"(a[mi][2]), "r"(a[mi][3]),
                          "r"(b[ni][0]), "r"(b[ni][1]));
                }
        }
        asm volatile("cp.async.commit_group;\n" ::: "memory");
    }

    #pragma unroll
    for (int mi = 0; mi < 2; mi++) {
        int r0 = m0 + wm * 32 + mi * 16 + g;
        #pragma unroll
        for (int ni = 0; ni < 8; ni++) {
            int cc = c0 + wn * 64 + ni * 8 + t * 2;
            Cb[(size_t)cc * NN + r0]           = acc[mi][ni][0];
            Cb[(size_t)(cc + 1) * NN + r0]     = acc[mi][ni][1];
            Cb[(size_t)cc * NN + r0 + 8]       = acc[mi][ni][2];
            Cb[(size_t)(cc + 1) * NN + r0 + 8] = acc[mi][ni][3];
        }
    }
}

// ------------------------------------------------------------ fast math --
__device__ __forceinline__ float fsig(float x) {
    return __fdividef(1.f, 1.f + __expf(-x));
}
__device__ __forceinline__ float ftanh(float x) {
    float e = __expf(2.f * x);
    return __fdividef(e - 1.f, e + 1.f);
}
__device__ __forceinline__ unsigned long long pk2(float lo, float hi) {
    unsigned long long r;
    asm("mov.b64 %0, {%1, %2};" : "=l"(r) : "f"(lo), "f"(hi));
    return r;
}
__device__ __forceinline__ void upk2(unsigned long long v, float& lo, float& hi) {
    asm("mov.b64 {%0, %1}, %2;" : "=f"(lo), "=f"(hi) : "l"(v));
}
__device__ __forceinline__ unsigned long long ffma2(unsigned long long a,
                                                    unsigned long long b,
                                                    unsigned long long c) {
    unsigned long long d;
    asm("fma.rn.f32x2 %0, %1, %2, %3;" : "=l"(d) : "l"(a), "l"(b), "l"(c));
    return d;
}

// ---------------------------------------------------------------- epi 1 ---
// Two-pass (R then U), f32x2 FMA; reg-capped for occupancy.
__global__ __launch_bounds__(256, 3) void epi1(const float* __restrict__ state,
                                               const float* __restrict__ rk,
                                               const float* __restrict__ uk)
{
    __shared__ __align__(8) float srk[576], suk[576];
    for (int i = threadIdx.x; i < 576; i += 256) { srk[i] = rk[i]; suk[i] = uk[i]; }
    __syncthreads();

    int idx = blockIdx.x * blockDim.x + threadIdx.x;  // b*4096 + m
    int m = idx & 4095;
    int b = idx >> 12;

    float hs[36];
    #pragma unroll
    for (int s = 0; s < 2; s++) {
        const float* d = g_D1 + ((size_t)(s * NCOL1 + b * 18)) * NN + m;
        hs[s * 2 + 0] = d[0];
        hs[s * 2 + 1] = d[(size_t)NN];
        #pragma unroll
        for (int u = 0; u < 16; u++) hs[4 + s * 16 + u] = d[(size_t)(2 + u) * NN];
    }

    {
        unsigned long long aR[8];
        #pragma unroll
        for (int p = 0; p < 8; p++) aR[p] = 0ull;
        #pragma unroll
        for (int j = 0; j < 36; j++) {
            unsigned long long hh = pk2(hs[j], hs[j]);
            const unsigned long long* w = (const unsigned long long*)&srk[j * 16];
            #pragma unroll
            for (int p = 0; p < 8; p++) aR[p] = ffma2(hh, w[p], aR[p]);
        }
        #pragma unroll
        for (int p = 0; p < 8; p++) {
            float x, y;
            upk2(aR[p], x, y);
            float r0 = fsig(x), r1 = fsig(y);
            float pv0 = state[b * 65536 + (2 * p) * 4096 + m];
            float pv1 = state[b * 65536 + (2 * p + 1) * 4096 + m];
            g_X2[(size_t)(b * 16 + 2 * p) * NN + m]     = __float2bfloat16_rn(r0 * pv0);
            g_X2[(size_t)(b * 16 + 2 * p + 1) * NN + m] = __float2bfloat16_rn(r1 * pv1);
        }
    }
    {
        unsigned long long aU[8];
        #pragma unroll
        for (int p = 0; p < 8; p++) aU[p] = 0ull;
        #pragma unroll
        for (int j = 0; j < 36; j++) {
            unsigned long long hh = pk2(hs[j], hs[j]);
            const unsigned long long* w = (const unsigned long long*)&suk[j * 16];
            #pragma unroll
            for (int p = 0; p < 8; p++) aU[p] = ffma2(hh, w[p], aU[p]);
        }
        #pragma unroll
        for (int p = 0; p < 8; p++) {
            float x, y;
            upk2(aU[p], x, y);
            g_U[(size_t)(b * 16 + 2 * p) * NN + m]     = fsig(x);
            g_U[(size_t)(b * 16 + 2 * p + 1) * NN + m] = fsig(y);
        }
    }
}

// ---------------------------------------------------------------- epi 2 ---
// h re-read from fp32 D1 (g_H eliminated); reg-capped for occupancy.
__global__ __launch_bounds__(256, 3) void epi2(const float* __restrict__ state,
                                               const float* __restrict__ ck,
                                               float* __restrict__ out)
{
    __shared__ __align__(8) float sck[576];
    for (int i = threadIdx.x; i < 576; i += 256) sck[i] = ck[i];
    __syncthreads();

    int idx = blockIdx.x * blockDim.x + threadIdx.x;  // b*4096 + m
    int m = idx & 4095;
    int b = idx >> 12;

    float hs[36];
    #pragma unroll
    for (int s = 0; s < 2; s++) {
        const float* d1 = g_D1 + ((size_t)(s * NCOL1 + b * 18)) * NN + m;
        hs[s * 2 + 0] = d1[0];
        hs[s * 2 + 1] = d1[(size_t)NN];
        const float* d2 = g_D2 + ((size_t)(s * NCOL2 + b * 16)) * NN + m;
        #pragma unroll
        for (int u = 0; u < 16; u++) hs[4 + s * 16 + u] = d2[(size_t)u * NN];
    }

    unsigned long long aC[8];
    #pragma unroll
    for (int p = 0; p < 8; p++) aC[p] = 0ull;
    #pragma unroll
    for (int j = 0; j < 36; j++) {
        unsigned long long hh = pk2(hs[j], hs[j]);
        const unsigned long long* w = (const unsigned long long*)&sck[j * 16];
        #pragma unroll
        for (int p = 0; p < 8; p++) aC[p] = ffma2(hh, w[p], aC[p]);
    }
    float4 o[4];
    #pragma unroll
    for (int p = 0; p < 8; p++) {
        float x, y;
        upk2(aC[p], x, y);
        float c0 = ftanh(x), c1 = ftanh(y);
        float u0 = g_U[(size_t)(b * 16 + 2 * p) * NN + m];
        float u1 = g_U[(size_t)(b * 16 + 2 * p + 1) * NN + m];
        float p0 = state[b * 65536 + (2 * p) * 4096 + m];
        float p1 = state[b * 65536 + (2 * p + 1) * 4096 + m];
        ((float*)o)[2 * p]     = u0 * p0 + (1.f - u0) * c0;
        ((float*)o)[2 * p + 1] = u1 * p1 + (1.f - u1) * c1;
    }
    float4* dst = (float4*)&out[b * 65536 + m * 16];
    #pragma unroll
    for (int q = 0; q < 4; q++) dst[q] = o[q];
}

// -------------------------------------------------------------- launch ----
extern "C" void kernel_launch(void* const* d_in, const int* in_sizes, int n_in,
                              void* d_out, int out_size) {
    const float* inputs = (const float*)d_in[0];
    const float* state  = (const float*)d_in[1];
    const float* s0     = (const float*)d_in[2];
    const float* s1     = (const float*)d_in[3];
    const float* rk     = (const float*)d_in[4];
    const float* uk     = (const float*)d_in[5];
    const float* ck     = (const float*)d_in[6];
    float* out = (float*)d_out;

    cudaFuncSetAttribute(gemm_bf16, cudaFuncAttributeMaxDynamicSharedMemorySize,
                         SMEM_TOT);

    __nv_bfloat16 *x1, *x2;
    float *d1, *d2;
    cudaGetSymbolAddress((void**)&x1, g_X1);
    cudaGetSymbolAddress((void**)&x2, g_X2);
    cudaGetSymbolAddress((void**)&d1, g_D1);
    cudaGetSymbolAddress((void**)&d2, g_D2);

    convpack<<<CONV_BLKS + PACK_BLKS, 256>>>(s0, s1, inputs, state);
    gemm_bf16<<<dim3(NN / BM, NCOL1 / BN, 2), 256, SMEM_TOT>>>(x1, d1, NCOL1);
    epi1<<<(64 * NN) / 256, 256>>>(state, rk, uk);
    gemm_bf16<<<dim3(NN / BM, NCOL2 / BN, 2), 256, SMEM_TOT>>>(x2, d2, NCOL2);
    epi2<<<(64 * NN) / 256, 256>>>(state, ck, out);
}